// round 9
// baseline (speedup 1.0000x reference)
#include <cuda_runtime.h>
#include <cuda_bf16.h>

// AttentionGate fused kernel, round 9: cut LSU instruction count.
//
// psi = sigmoid(Wpsi . relu(Wg@g + Wx@x));  out = x * psi
// B=2, CF=CG=64, CI=32, DHW=64^3=262144.
//
// Round 8 was LSU/L1tex *instruction-issue* bound (L1=81%): 1152 memory
// instructions per warp at the ~4cyc LSU accept floor ~= the runtime.
// This round: CI split 8-ways (4 channels/lane, lane&7), 8 pair-streams per
// thread loaded as 4x LDG.128 (2 consecutive pairs each). Per k-iter per
// warp: 4 LDG.128 + 2 LDS.128 + 32 FFMA2 (was 4 LDG.64 + 4 LDS.128).
// Epilogue fully 128-bit. Memory instrs/warp: 1152 -> 832 (-28%), LDS halved.

#define HALFV 131072            // u64 (f32x2) elements per channel-plane
#define PLANE2 65536            // ulonglong2 elements per channel-plane

typedef unsigned long long u64;

__device__ __forceinline__ u64 ffma2(u64 a, u64 b, u64 c) {
    u64 d;
    asm("fma.rn.f32x2 %0, %1, %2, %3;" : "=l"(d) : "l"(a), "l"(b), "l"(c));
    return d;
}
__device__ __forceinline__ u64 fmul2(u64 a, u64 b) {
    u64 d;
    asm("mul.rn.f32x2 %0, %1, %2;" : "=l"(d) : "l"(a), "l"(b));
    return d;
}
__device__ __forceinline__ u64 pack2(float lo, float hi) {
    u64 r;
    asm("mov.b64 %0, {%1, %2};" : "=l"(r) : "f"(lo), "f"(hi));
    return r;
}
__device__ __forceinline__ float2 unpack2(u64 v) {
    float2 r;
    asm("mov.b64 {%0, %1}, %2;" : "=f"(r.x), "=f"(r.y) : "l"(v));
    return r;
}

__global__ __launch_bounds__(256, 2)
void attn_gate_kernel(const float* __restrict__ x,
                      const float* __restrict__ g,
                      const float* __restrict__ Wg,
                      const float* __restrict__ Wx,
                      const float* __restrict__ Wpsi,
                      float* __restrict__ out)
{
    // Wc[k] row (32 u64): channel o = 4q + 2c + lh stored at u64 index
    // 2*(8c + q) + lh, so LDS.128 #c reads chunks [c*8 .. c*8+7] = 128B
    // contiguous across the 8 q-lanes -> conflict-free.
    __shared__ u64   Wc[128][32];      // 32 KiB
    __shared__ float wpsi_s[32];

    for (int idx = threadIdx.x; idx < 128 * 32; idx += 256) {
        int k = idx >> 5;
        int o = idx & 31;
        int qq = o >> 2, cc = (o >> 1) & 1, lh = o & 1;
        float w = (k < 64) ? Wg[o * 64 + k] : Wx[o * 64 + (k - 64)];
        Wc[k][2 * (8 * cc + qq) + lh] = pack2(w, w);
    }
    if (threadIdx.x < 32) wpsi_s[threadIdx.x] = Wpsi[threadIdx.x];
    __syncthreads();

    int t    = blockIdx.x * 256 + threadIdx.x;
    int lane = t & 31;
    int wid  = t >> 5;            // 0..8191
    int gl   = lane >> 3;         // 0..3 spatial subgroup
    int q    = lane & 7;          // CI eighth: channels [4q, 4q+4)

    int pbase = wid * 32;                        // warp's first voxel pair
    int b     = pbase >> 17;                     // batch
    int sp    = (pbase & (HALFV - 1)) + gl * 2;  // first pair (even)

    // ulonglong2 pointers; thread's 4 loads at offsets {0,4,8,12} (= pairs
    // sp+{0,1,8,9,16,17,24,25}). Warp: 4 gl * 16B = 64B contiguous per load.
    size_t cbase = (size_t)(b * 64) * PLANE2 + (sp >> 1);
    const ulonglong2* g2 = (const ulonglong2*)g + cbase;
    const ulonglong2* x2 = (const ulonglong2*)x + cbase;

    u64 acc[4][8];                // [channel-in-quarter][stream u64]
    #pragma unroll
    for (int i = 0; i < 4; i++)
        #pragma unroll
        for (int s = 0; s < 8; s++) acc[i][s] = 0ULL;

    // ---- g projection (k = 0..63) ----
    {
        const ulonglong2* gp = g2;
        #pragma unroll 2
        for (int k = 0; k < 64; k++) {
            ulonglong2 v0 = gp[0], v1 = gp[4], v2 = gp[8], v3 = gp[12];
            const ulonglong2* wrow = (const ulonglong2*)(&Wc[k][0]);
            ulonglong2 wa = wrow[q];        // channels 4q+0, 4q+1
            ulonglong2 wb = wrow[8 + q];    // channels 4q+2, 4q+3
            u64 v[8] = {v0.x, v0.y, v1.x, v1.y, v2.x, v2.y, v3.x, v3.y};
            #pragma unroll
            for (int s = 0; s < 8; s++) {
                acc[0][s] = ffma2(wa.x, v[s], acc[0][s]);
                acc[1][s] = ffma2(wa.y, v[s], acc[1][s]);
                acc[2][s] = ffma2(wb.x, v[s], acc[2][s]);
                acc[3][s] = ffma2(wb.y, v[s], acc[3][s]);
            }
            gp += PLANE2;
        }
    }

    // ---- x projection (k = 64..127) ----
    {
        const ulonglong2* xp = x2;
        #pragma unroll 2
        for (int k = 0; k < 64; k++) {
            ulonglong2 v0 = xp[0], v1 = xp[4], v2 = xp[8], v3 = xp[12];
            const ulonglong2* wrow = (const ulonglong2*)(&Wc[64 + k][0]);
            ulonglong2 wa = wrow[q];
            ulonglong2 wb = wrow[8 + q];
            u64 v[8] = {v0.x, v0.y, v1.x, v1.y, v2.x, v2.y, v3.x, v3.y};
            #pragma unroll
            for (int s = 0; s < 8; s++) {
                acc[0][s] = ffma2(wa.x, v[s], acc[0][s]);
                acc[1][s] = ffma2(wa.y, v[s], acc[1][s]);
                acc[2][s] = ffma2(wb.x, v[s], acc[2][s]);
                acc[3][s] = ffma2(wb.y, v[s], acc[3][s]);
            }
            xp += PLANE2;
        }
    }

    // ---- relu + partial Wpsi dot (this lane's 4 channels, 8 streams) ----
    float sx[8], sy[8];
    #pragma unroll
    for (int s = 0; s < 8; s++) { sx[s] = 0.f; sy[s] = 0.f; }
    #pragma unroll
    for (int i = 0; i < 4; i++) {
        float wp = wpsi_s[4 * q + i];
        #pragma unroll
        for (int s = 0; s < 8; s++) {
            float2 a = unpack2(acc[i][s]);
            sx[s] = fmaf(fmaxf(a.x, 0.f), wp, sx[s]);
            sy[s] = fmaf(fmaxf(a.y, 0.f), wp, sy[s]);
        }
    }
    // Reduce across the 8 q-lanes sharing each pair (masks 1,2,4 stay
    // inside the 8-lane group).
    u64 psiA[4], psiB[4];         // psi for .x / .y components of load j
    #pragma unroll
    for (int s = 0; s < 8; s++) {
        sx[s] += __shfl_xor_sync(0xffffffffu, sx[s], 1);
        sx[s] += __shfl_xor_sync(0xffffffffu, sx[s], 2);
        sx[s] += __shfl_xor_sync(0xffffffffu, sx[s], 4);
        sy[s] += __shfl_xor_sync(0xffffffffu, sy[s], 1);
        sy[s] += __shfl_xor_sync(0xffffffffu, sy[s], 2);
        sy[s] += __shfl_xor_sync(0xffffffffu, sy[s], 4);
        float px = 1.f / (1.f + __expf(-sx[s]));
        float py = 1.f / (1.f + __expf(-sy[s]));
        u64 p = pack2(px, py);
        if (s & 1) psiB[s >> 1] = p; else psiA[s >> 1] = p;
    }

    // ---- out[c] = x[c] * psi : lane q writes channels [8q, 8q+8) ----
    const ulonglong2* xe = x2 + (size_t)(8 * q) * PLANE2;
    ulonglong2*       oe = (ulonglong2*)out + cbase + (size_t)(8 * q) * PLANE2;
    #pragma unroll 2
    for (int c = 0; c < 8; c++) {
        size_t pb = (size_t)c * PLANE2;
        #pragma unroll
        for (int j = 0; j < 4; j++) {
            ulonglong2 xv = xe[pb + 4 * j];
            ulonglong2 ov;
            ov.x = fmul2(xv.x, psiA[j]);
            ov.y = fmul2(xv.y, psiB[j]);
            oe[pb + 4 * j] = ov;
        }
    }
}

extern "C" void kernel_launch(void* const* d_in, const int* in_sizes, int n_in,
                              void* d_out, int out_size)
{
    const float* x    = (const float*)d_in[0];
    const float* g    = (const float*)d_in[1];
    const float* Wg   = (const float*)d_in[2];
    const float* Wx   = (const float*)d_in[3];
    const float* Wpsi = (const float*)d_in[4];
    float* out = (float*)d_out;

    // 262144 voxel pairs / 32 pairs-per-warp = 8192 warps = 1024 blocks
    attn_gate_kernel<<<1024, 256>>>(x, g, Wg, Wx, Wpsi, out);
}